// round 2
// baseline (speedup 1.0000x reference)
#include <cuda_runtime.h>
#include <cuda_bf16.h>
#include <cstdint>

// Problem constants
#define BB   4096
#define AA   8
#define HH   512
#define NQv  128
#define NKv  128
#define NVv  256
#define NACT 30
#define ROWS (BB*AA)          // 32768
#define EV_OFF   0            // evidence [ROWS][30]
#define ORI_OFF  (ROWS*NACT)  // 983040, ori_u [A][B]
#define COM_OFF  (ORI_OFF + ROWS) // 1015808, com_u [A][B]

// ---------------- device scratch (static, allocation-free) ----------------
__device__ float    g_W1[HH * HH];          // packed [K=512][N=512]: Wk|Wv|Wq
__device__ float    g_b1[HH];
__device__ float    g_kvq[(size_t)ROWS * HH];   // per row: key[0:128] value[128:384] query[384:512]
__device__ float    g_attn[(size_t)ROWS * NVv]; // attn_applied
__device__ float    g_comb[(size_t)ROWS * HH];  // attn_combined (post relu)
__device__ float    g_allev[(size_t)BB * NACT];
__device__ unsigned g_scal[4];  // 0: max(be) key, 1: min(be) key, 2: max(all_ev), 3: min(all_ev)

// order-preserving float<->uint mapping for atomic min/max
__device__ __forceinline__ unsigned fkey(float f) {
    unsigned u = __float_as_uint(f);
    return (u >> 31) ? ~u : (u | 0x80000000u);
}
__device__ __forceinline__ float funkey(unsigned k) {
    unsigned u = (k >> 31) ? (k ^ 0x80000000u) : ~k;
    return __uint_as_float(u);
}

// ---------------- init ----------------
__global__ void init_kernel() {
    if (threadIdx.x == 0) {
        g_scal[0] = 0u;           // max key: smallest possible
        g_scal[1] = 0xFFFFFFFFu;  // min key
        g_scal[2] = 0u;
        g_scal[3] = 0xFFFFFFFFu;
    }
}

// ---------------- pack Wk|Wv|Wq -> g_W1, biases -> g_b1 ----------------
__global__ void pack_kernel(const float* __restrict__ Wk, const float* __restrict__ bk,
                            const float* __restrict__ Wv, const float* __restrict__ bv,
                            const float* __restrict__ Wq, const float* __restrict__ bq) {
    int i = blockIdx.x * blockDim.x + threadIdx.x;
    if (i < HH * HH) {
        int k = i / HH, n = i % HH;
        float v;
        if (n < NKv)            v = Wk[k * NKv + n];
        else if (n < NKv + NVv) v = Wv[k * NVv + (n - NKv)];
        else                    v = Wq[k * NQv + (n - NKv - NVv)];
        g_W1[i] = v;
    }
    if (i < HH) {
        float v;
        if (i < NKv)            v = bk[i];
        else if (i < NKv + NVv) v = bv[i - NKv];
        else                    v = bq[i - NKv - NVv];
        g_b1[i] = v;
    }
}

// ---------------- SGEMM: C[M,N] = act(A @ W + bias) ----------------
// A is split by K: k < K0 -> A0 (lda0), else A1 at col (k-K0) (lda1).
#define BM 128
#define BN 128
#define BK 8
#define TM 8
#define TN 8

template<bool RELU>
__global__ __launch_bounds__(256)
void sgemm_split(const float* __restrict__ A0, int lda0, int K0,
                 const float* __restrict__ A1, int lda1,
                 const float* __restrict__ W, const float* __restrict__ bias,
                 float* __restrict__ C, int N, int K) {
    __shared__ float As[BK][BM];
    __shared__ float Bs[BK][BN];
    int tid = threadIdx.x;
    int tx = tid & 15, ty = tid >> 4;
    int rowC = blockIdx.y * BM + ty * TM;
    int colC = blockIdx.x * BN + tx * TN;

    int arow = tid >> 1;           // 0..127
    int acol = (tid & 1) * 4;      // 0 or 4
    int brow = tid >> 5;           // 0..7
    int bcol = (tid & 31) * 4;     // 0..124

    float acc[TM][TN];
    #pragma unroll
    for (int i = 0; i < TM; i++)
        #pragma unroll
        for (int j = 0; j < TN; j++) acc[i][j] = 0.f;

    for (int kb = 0; kb < K; kb += BK) {
        const float* Aptr; int lda, kloc;
        if (kb < K0) { Aptr = A0; lda = lda0; kloc = kb; }
        else         { Aptr = A1; lda = lda1; kloc = kb - K0; }
        float4 av = *(const float4*)(Aptr + (size_t)(blockIdx.y * BM + arow) * lda + kloc + acol);
        As[acol + 0][arow] = av.x;
        As[acol + 1][arow] = av.y;
        As[acol + 2][arow] = av.z;
        As[acol + 3][arow] = av.w;
        float4 bv4 = *(const float4*)(W + (size_t)(kb + brow) * N + blockIdx.x * BN + bcol);
        *(float4*)&Bs[brow][bcol] = bv4;
        __syncthreads();
        #pragma unroll
        for (int k = 0; k < BK; k++) {
            float ra[TM], rb[TN];
            #pragma unroll
            for (int i = 0; i < TM; i++) ra[i] = As[k][ty * TM + i];
            #pragma unroll
            for (int j = 0; j < TN; j++) rb[j] = Bs[k][tx * TN + j];
            #pragma unroll
            for (int i = 0; i < TM; i++)
                #pragma unroll
                for (int j = 0; j < TN; j++) acc[i][j] += ra[i] * rb[j];
        }
        __syncthreads();
    }
    #pragma unroll
    for (int i = 0; i < TM; i++) {
        #pragma unroll
        for (int j = 0; j < TN; j++) {
            float v = acc[i][j] + bias[colC + j];
            if (RELU) v = fmaxf(v, 0.f);
            C[(size_t)(rowC + i) * N + colC + j] = v;
        }
    }
}

// ---------------- per-batch attention ----------------
__global__ __launch_bounds__(256)
void attn_kernel(const float* __restrict__ kvq, const float* __restrict__ Wattn,
                 const float* __restrict__ battn, float* __restrict__ attn_out) {
    int b = blockIdx.x;
    int tid = threadIdx.x;
    __shared__ float sk[AA * NKv];
    __shared__ float sq[AA * NQv];
    __shared__ float sv[AA * NVv];
    __shared__ float slog[AA][AA];
    __shared__ float swt[AA][AA + 1];
    __shared__ float skp[AA];
    const float* base = kvq + (size_t)b * AA * HH;
    for (int i = tid; i < AA * NKv; i += 256) {
        int a = i >> 7, c = i & 127;
        sk[i] = base[a * HH + c];
        sq[i] = base[a * HH + 384 + c];
    }
    for (int i = tid; i < AA * NVv; i += 256) {
        int a = i >> 8, c = i & 255;
        sv[i] = base[a * HH + 128 + c];
    }
    __syncthreads();
    int w = tid >> 5, lane = tid & 31;
    // keypart[j=w] = keyflat . Wattn[128+i][w]
    float kp = 0.f;
    for (int i = lane; i < AA * NKv; i += 32)
        kp += sk[i] * __ldg(&Wattn[(NQv + i) * AA + w]);
    #pragma unroll
    for (int o = 16; o; o >>= 1) kp += __shfl_xor_sync(0xFFFFFFFFu, kp, o);
    if (lane == 0) skp[w] = kp;
    __syncthreads();
    // query part: warp w -> agent a=w, all 8 logits
    float accj[AA] = {0,0,0,0,0,0,0,0};
    for (int q = lane; q < NQv; q += 32) {
        float qv = sq[w * NQv + q];
        #pragma unroll
        for (int j = 0; j < AA; j++) accj[j] += qv * __ldg(&Wattn[q * AA + j]);
    }
    #pragma unroll
    for (int j = 0; j < AA; j++) {
        float v = accj[j];
        #pragma unroll
        for (int o = 16; o; o >>= 1) v += __shfl_xor_sync(0xFFFFFFFFu, v, o);
        if (lane == 0) slog[w][j] = v + skp[j] + __ldg(&battn[j]);
    }
    __syncthreads();
    if (tid < AA) {
        float m = -1e30f;
        #pragma unroll
        for (int j = 0; j < AA; j++) m = fmaxf(m, slog[tid][j]);
        float e[AA], s = 0.f;
        #pragma unroll
        for (int j = 0; j < AA; j++) { e[j] = expf(slog[tid][j] - m); s += e[j]; }
        #pragma unroll
        for (int j = 0; j < AA; j++) swt[tid][j] = e[j] / s;
    }
    __syncthreads();
    for (int idx = tid; idx < AA * NVv; idx += 256) {
        int a = idx >> 8, v = idx & 255;
        float acc = 0.f;
        #pragma unroll
        for (int j = 0; j < AA; j++) acc += swt[a][j] * sv[j * NVv + v];
        attn_out[(size_t)(b * AA + a) * NVv + v] = acc;
    }
}

// ---------------- W2 head: q = comb @ W2 + b2, evidence=clip, S, ori_u, global max/min(be) ----------------
__global__ __launch_bounds__(256)
void head_kernel(const float* __restrict__ comb, const float* __restrict__ W2,
                 const float* __restrict__ b2, float* __restrict__ out) {
    __shared__ float srow[8][HH];
    __shared__ float smx[8], smn[8];
    int w = threadIdx.x >> 5, lane = threadIdx.x & 31;
    int row = blockIdx.x * 8 + w;
    const float* a = comb + (size_t)row * HH;
    for (int i = lane; i < HH; i += 32) srow[w][i] = a[i];
    __syncwarp();
    float acc = 0.f;
    if (lane < NACT) {
        #pragma unroll 8
        for (int k = 0; k < HH; k++) acc += srow[w][k] * __ldg(&W2[k * NACT + lane]);
        acc += __ldg(&b2[lane]);
    }
    float be = (lane < NACT) ? fmaxf(acc, 0.f) : 0.f;
    if (lane < NACT) out[(size_t)row * NACT + lane] = be;
    float s = be;
    #pragma unroll
    for (int o = 16; o; o >>= 1) s += __shfl_xor_sync(0xFFFFFFFFu, s, o);
    s += (float)NACT;
    if (lane == 0) {
        int bb = row >> 3, aa = row & 7;
        out[ORI_OFF + aa * BB + bb] = (float)NACT / s;
    }
    float mx = be;                               // be >= 0 so padding 0s can't raise max wrongly
    float mn = (lane < NACT) ? be : 1e30f;
    #pragma unroll
    for (int o = 16; o; o >>= 1) {
        mx = fmaxf(mx, __shfl_xor_sync(0xFFFFFFFFu, mx, o));
        mn = fminf(mn, __shfl_xor_sync(0xFFFFFFFFu, mn, o));
    }
    if (lane == 0) { smx[w] = mx; smn[w] = mn; }
    __syncthreads();
    if (threadIdx.x == 0) {
        float M = -1e30f, m = 1e30f;
        #pragma unroll
        for (int i = 0; i < 8; i++) { M = fmaxf(M, smx[i]); m = fminf(m, smn[i]); }
        atomicMax(&g_scal[0], fkey(M));
        atomicMin(&g_scal[1], fkey(m));
    }
}

// ---------------- Dempster-Shafer scan over agents, per batch ----------------
__global__ __launch_bounds__(256)
void ds_kernel(const float* __restrict__ out, float* __restrict__ allev) {
    __shared__ float smx[8], smn[8];
    int w = threadIdx.x >> 5, lane = threadIdx.x & 31;
    int b = blockIdx.x * 8 + w;
    float b0 = 0.f, u0 = 1.f;
    for (int a = 0; a < AA; a++) {
        float e = (lane < NACT) ? out[(size_t)(b * AA + a) * NACT + lane] : 0.f;
        float s = e;
        #pragma unroll
        for (int o = 16; o; o >>= 1) s += __shfl_xor_sync(0xFFFFFFFFu, s, o);
        s += (float)NACT;
        float b1 = e / s;
        float u1 = (float)NACT / s;
        float sum0 = b0, sum1 = b1, dot = b0 * b1;
        #pragma unroll
        for (int o = 16; o; o >>= 1) {
            sum0 += __shfl_xor_sync(0xFFFFFFFFu, sum0, o);
            sum1 += __shfl_xor_sync(0xFFFFFFFFu, sum1, o);
            dot  += __shfl_xor_sync(0xFFFFFFFFu, dot,  o);
        }
        float Cc = sum0 * sum1 - dot;
        float denom = 1.f - Cc;
        float nb = (b0 * b1 + b0 * u1 + b1 * u0) / denom;
        u0 = (u0 * u1) / denom;
        b0 = nb;
    }
    float ev = b0 * ((float)NACT / u0);
    if (lane < NACT) allev[(size_t)b * NACT + lane] = ev;
    float mx = (lane < NACT) ? ev : -1e30f;
    float mn = (lane < NACT) ? ev : 1e30f;
    #pragma unroll
    for (int o = 16; o; o >>= 1) {
        mx = fmaxf(mx, __shfl_xor_sync(0xFFFFFFFFu, mx, o));
        mn = fminf(mn, __shfl_xor_sync(0xFFFFFFFFu, mn, o));
    }
    if (lane == 0) { smx[w] = mx; smn[w] = mn; }
    __syncthreads();
    if (threadIdx.x == 0) {
        float M = -1e30f, m = 1e30f;
        #pragma unroll
        for (int i = 0; i < 8; i++) { M = fmaxf(M, smx[i]); m = fminf(m, smn[i]); }
        atomicMax(&g_scal[2], fkey(M));
        atomicMin(&g_scal[3], fkey(m));
    }
}

// ---------------- finalize: re, combined, out evidence, com_u ----------------
__global__ __launch_bounds__(256)
void fin_kernel(float* __restrict__ out, const float* __restrict__ allev) {
    float maxbe = funkey(g_scal[0]);
    float minbe = funkey(g_scal[1]);
    float maxre = funkey(g_scal[2]);
    float minre = funkey(g_scal[3]);
    float scale = (maxbe - minbe) * 0.1f;
    float norm = scale / (maxre - minre + 0.01f);
    int w = threadIdx.x >> 5, lane = threadIdx.x & 31;
    int row = blockIdx.x * 8 + w;
    int b = row >> 3, a = row & 7;
    float be = (lane < NACT) ? out[(size_t)row * NACT + lane] : 0.f;
    float ev = (lane < NACT) ? allev[(size_t)b * NACT + lane] : 0.f;
    float re = (ev - minre) * norm;
    float combined = be + re;
    if (lane < NACT) out[(size_t)row * NACT + lane] = be + combined;
    float s = (lane < NACT) ? combined : 0.f;
    #pragma unroll
    for (int o = 16; o; o >>= 1) s += __shfl_xor_sync(0xFFFFFFFFu, s, o);
    s += (float)NACT;
    if (lane == 0) out[COM_OFF + a * BB + b] = (float)NACT / s;
}

// ---------------- launch ----------------
extern "C" void kernel_launch(void* const* d_in, const int* in_sizes, int n_in,
                              void* d_out, int out_size) {
    const float* hidden = (const float*)d_in[0];
    // d_in[1] = send_target (unused by reference)
    const float* Wk    = (const float*)d_in[2];
    const float* bk    = (const float*)d_in[3];
    const float* Wv    = (const float*)d_in[4];
    const float* bv    = (const float*)d_in[5];
    const float* Wq    = (const float*)d_in[6];
    const float* bq    = (const float*)d_in[7];
    const float* Wattn = (const float*)d_in[8];
    const float* battn = (const float*)d_in[9];
    const float* Wc    = (const float*)d_in[10];
    const float* bc    = (const float*)d_in[11];
    const float* W2    = (const float*)d_in[12];
    const float* b2    = (const float*)d_in[13];
    float* out = (float*)d_out;

    float *kvq, *attn, *comb, *allev, *W1, *b1;
    cudaGetSymbolAddress((void**)&kvq,   g_kvq);
    cudaGetSymbolAddress((void**)&attn,  g_attn);
    cudaGetSymbolAddress((void**)&comb,  g_comb);
    cudaGetSymbolAddress((void**)&allev, g_allev);
    cudaGetSymbolAddress((void**)&W1,    g_W1);
    cudaGetSymbolAddress((void**)&b1,    g_b1);

    init_kernel<<<1, 32>>>();
    pack_kernel<<<(HH * HH + 255) / 256, 256>>>(Wk, bk, Wv, bv, Wq, bq);

    dim3 g1(HH / BN, ROWS / BM);
    sgemm_split<false><<<g1, 256>>>(hidden, HH, HH, hidden, HH, W1, b1, kvq, HH, HH);

    attn_kernel<<<BB, 256>>>(kvq, Wattn, battn, attn);

    dim3 g2(HH / BN, ROWS / BM);
    sgemm_split<true><<<g2, 256>>>(attn, NVv, NVv, hidden, HH, Wc, bc, comb, HH, NVv + HH);

    head_kernel<<<ROWS / 8, 256>>>(comb, W2, b2, out);
    ds_kernel<<<BB / 8, 256>>>(out, allev);
    fin_kernel<<<ROWS / 8, 256>>>(out, allev);
}

// round 11
// speedup vs baseline: 1.9686x; 1.9686x over previous
#include <cuda_runtime.h>
#include <cuda_bf16.h>
#include <cstdint>

// Problem constants
#define BB   4096
#define AA   8
#define HH   512
#define NQv  128
#define NKv  128
#define NVv  256
#define NACT 30
#define ROWS (BB*AA)              // 32768
#define ORI_OFF  (ROWS*NACT)
#define COM_OFF  (ORI_OFF + ROWS)

// ---------------- device scratch (static, allocation-free) ----------------
__device__ float    g_kvq[(size_t)ROWS * HH];
__device__ float    g_attn[(size_t)ROWS * NVv];
__device__ float    g_comb[(size_t)ROWS * HH];
__device__ float    g_allev[(size_t)BB * NACT];
__device__ unsigned g_scal[4];
__device__ float    g_b1[HH];
// transposed, hi/lo bf16 weights: WT[n][k]
__device__ __nv_bfloat16 g_WT1h[HH * HH];
__device__ __nv_bfloat16 g_WT1l[HH * HH];
__device__ __nv_bfloat16 g_WTch[HH * (NVv + HH)];
__device__ __nv_bfloat16 g_WTcl[HH * (NVv + HH)];

// order-preserving float<->uint mapping for atomic min/max
__device__ __forceinline__ unsigned fkey(float f) {
    unsigned u = __float_as_uint(f);
    return (u >> 31) ? ~u : (u | 0x80000000u);
}
__device__ __forceinline__ float funkey(unsigned k) {
    unsigned u = (k >> 31) ? (k ^ 0x80000000u) : ~k;
    return __uint_as_float(u);
}

// bf16 mma.sync (family-portable HMMA, works on plain sm_103 target)
__device__ __forceinline__ void mma_bf16(float* d, const uint32_t* a, const uint32_t* b) {
    asm volatile(
        "mma.sync.aligned.m16n8k16.row.col.f32.bf16.bf16.f32 "
        "{%0,%1,%2,%3}, {%4,%5,%6,%7}, {%8,%9}, {%0,%1,%2,%3};"
        : "+f"(d[0]), "+f"(d[1]), "+f"(d[2]), "+f"(d[3])
        : "r"(a[0]), "r"(a[1]), "r"(a[2]), "r"(a[3]), "r"(b[0]), "r"(b[1]));
}

__device__ __forceinline__ void cvt_hilo(float x, float y, uint32_t& hi, uint32_t& lo) {
    __nv_bfloat162 h = __floats2bfloat162_rn(x, y);       // .x = x (low half)
    float hx = __bfloat162float(h.x), hy = __bfloat162float(h.y);
    __nv_bfloat162 l = __floats2bfloat162_rn(x - hx, y - hy);
    hi = *(uint32_t*)&h;
    lo = *(uint32_t*)&l;
}

// ---------------- init ----------------
__global__ void init_kernel() {
    if (threadIdx.x == 0) {
        g_scal[0] = 0u; g_scal[1] = 0xFFFFFFFFu;
        g_scal[2] = 0u; g_scal[3] = 0xFFFFFFFFu;
    }
}

// ---------------- pack W1 (Wk|Wv|Wq) -> transposed hi/lo bf16, b1 ----------------
__global__ void pack1_kernel(const float* __restrict__ Wk, const float* __restrict__ bk,
                             const float* __restrict__ Wv, const float* __restrict__ bv,
                             const float* __restrict__ Wq, const float* __restrict__ bq) {
    int i = blockIdx.x * blockDim.x + threadIdx.x;
    if (i < HH * HH) {
        int n = i >> 9, k = i & 511;
        float w;
        if (n < NKv)            w = Wk[k * NKv + n];
        else if (n < NKv + NVv) w = Wv[k * NVv + (n - NKv)];
        else                    w = Wq[k * NQv + (n - NKv - NVv)];
        __nv_bfloat16 h = __float2bfloat16(w);
        g_WT1h[i] = h;
        g_WT1l[i] = __float2bfloat16(w - __bfloat162float(h));
    }
    if (i < HH) {
        float v;
        if (i < NKv)            v = bk[i];
        else if (i < NKv + NVv) v = bv[i - NKv];
        else                    v = bq[i - NKv - NVv];
        g_b1[i] = v;
    }
}

// ---------------- pack Wc -> transposed hi/lo bf16 ----------------
__global__ void packc_kernel(const float* __restrict__ Wc) {
    int i = blockIdx.x * blockDim.x + threadIdx.x;
    if (i < HH * (NVv + HH)) {
        int n = i / (NVv + HH), k = i % (NVv + HH);
        float w = Wc[k * HH + n];
        __nv_bfloat16 h = __float2bfloat16(w);
        g_WTch[i] = h;
        g_WTcl[i] = __float2bfloat16(w - __bfloat162float(h));
    }
}

// ---------------- HMMA GEMM: C[M,N] = act(A @ WT^T + bias) ----------------
// A fp32, split by K (A0 for k<K0, A1 after). WT is [N][K] bf16 hi/lo.
// Block tile 128x128x32, 8 warps (2x4), warp tile 64x32.
// SINGLE smem buffer (static, 40KB) + register staging for the next chunk:
//   loadg(c+1) -> compute(c) -> sync -> store_s(c+1) -> sync
// hi/lo compensation: D += Ah*Bh + Ah*Bl + Al*Bh.
#define GSTR 40                      // padded k-stride in bf16 elems (80B, conflict-free)
#define TILE_B (128 * GSTR * 2)      // 10240 bytes per sub-tile
#define BUF_B  (4 * TILE_B)          // Ah|Al|Bh|Bl = 40960 bytes (static smem, <48KB)

template<bool RELU>
__global__ __launch_bounds__(256)
void gemm_mma(const float* __restrict__ A0, int lda0, int K0,
              const float* __restrict__ A1, int lda1,
              const __nv_bfloat16* __restrict__ WTh, const __nv_bfloat16* __restrict__ WTl,
              const float* __restrict__ bias, float* __restrict__ C, int N, int K) {
    __shared__ char sm[BUF_B];
    int tid = threadIdx.x;
    int wid = tid >> 5, lane = tid & 31;
    int gid = lane >> 2, tig = lane & 3;
    int wr = wid >> 2, wc = wid & 3;           // 2 x 4 warp grid
    int rowC = blockIdx.y * 128;
    int colC = blockIdx.x * 128;

    // gmem load mapping
    int r = tid >> 1, kbase = (tid & 1) * 16;  // A: row r, 16 k-elems

    float acc[4][4][4];
    #pragma unroll
    for (int mi = 0; mi < 4; mi++)
        #pragma unroll
        for (int ni = 0; ni < 4; ni++)
            #pragma unroll
            for (int j = 0; j < 4; j++) acc[mi][ni][j] = 0.f;

    float4 av[4];
    uint4 bhv[2], blv[2];

    auto loadg = [&](int kb) {
        const float* src; int lda;
        if (kb < K0) { src = A0 + kb; lda = lda0; }
        else         { src = A1 + (kb - K0); lda = lda1; }
        const float4* p = (const float4*)(src + (size_t)(rowC + r) * lda + kbase);
        av[0] = p[0]; av[1] = p[1]; av[2] = p[2]; av[3] = p[3];
        const uint4* ph = (const uint4*)(WTh + (size_t)(colC + r) * K + kb + kbase);
        const uint4* pl = (const uint4*)(WTl + (size_t)(colC + r) * K + kb + kbase);
        bhv[0] = ph[0]; bhv[1] = ph[1];
        blv[0] = pl[0]; blv[1] = pl[1];
    };
    auto store_s = [&]() {
        #pragma unroll
        for (int i = 0; i < 4; i++) {
            int k = kbase + i * 4;
            uint32_t h01, l01, h23, l23;
            cvt_hilo(av[i].x, av[i].y, h01, l01);
            cvt_hilo(av[i].z, av[i].w, h23, l23);
            uint32_t off = (uint32_t)(r * GSTR + k) * 2;
            *(uint2*)(sm + off)          = make_uint2(h01, h23);
            *(uint2*)(sm + TILE_B + off) = make_uint2(l01, l23);
        }
        #pragma unroll
        for (int j = 0; j < 2; j++) {
            uint32_t off = (uint32_t)(r * GSTR + kbase + j * 8) * 2;
            *(uint4*)(sm + 2 * TILE_B + off) = bhv[j];
            *(uint4*)(sm + 3 * TILE_B + off) = blv[j];
        }
    };
    auto compute = [&]() {
        const char* pAH = sm;
        const char* pAL = sm + TILE_B;
        const char* pBH = sm + 2 * TILE_B;
        const char* pBL = sm + 3 * TILE_B;
        int arow = wr * 64 + gid;
        int brow = wc * 32 + gid;
        #pragma unroll
        for (int ks = 0; ks < 32; ks += 16) {
            int ak = ks + tig * 2;
            uint32_t bh[4][2], bl[4][2];
            #pragma unroll
            for (int ni = 0; ni < 4; ni++) {
                uint32_t nb = (uint32_t)((brow + ni * 8) * GSTR + ak) * 2;
                bh[ni][0] = *(const uint32_t*)(pBH + nb);
                bh[ni][1] = *(const uint32_t*)(pBH + nb + 16);
                bl[ni][0] = *(const uint32_t*)(pBL + nb);
                bl[ni][1] = *(const uint32_t*)(pBL + nb + 16);
            }
            #pragma unroll
            for (int mi = 0; mi < 4; mi++) {
                uint32_t m0 = (uint32_t)((arow + mi * 16) * GSTR + ak) * 2;
                uint32_t m1 = m0 + 8 * GSTR * 2;
                uint32_t a[4], al[4];
                a[0] = *(const uint32_t*)(pAH + m0);
                a[1] = *(const uint32_t*)(pAH + m1);
                a[2] = *(const uint32_t*)(pAH + m0 + 16);
                a[3] = *(const uint32_t*)(pAH + m1 + 16);
                al[0] = *(const uint32_t*)(pAL + m0);
                al[1] = *(const uint32_t*)(pAL + m1);
                al[2] = *(const uint32_t*)(pAL + m0 + 16);
                al[3] = *(const uint32_t*)(pAL + m1 + 16);
                #pragma unroll
                for (int ni = 0; ni < 4; ni++) mma_bf16(acc[mi][ni], a,  bh[ni]);
                #pragma unroll
                for (int ni = 0; ni < 4; ni++) mma_bf16(acc[mi][ni], a,  bl[ni]);
                #pragma unroll
                for (int ni = 0; ni < 4; ni++) mma_bf16(acc[mi][ni], al, bh[ni]);
            }
        }
    };

    int nch = K / 32;
    loadg(0);
    store_s();
    __syncthreads();
    for (int c = 0; c < nch; c++) {
        if (c + 1 < nch) loadg((c + 1) * 32);   // stage next chunk in registers
        compute();                               // consume current smem buffer
        __syncthreads();
        if (c + 1 < nch) store_s();              // overwrite buffer with staged chunk
        __syncthreads();
    }

    // epilogue
    #pragma unroll
    for (int mi = 0; mi < 4; mi++) {
        int row0 = rowC + wr * 64 + mi * 16 + gid;
        #pragma unroll
        for (int ni = 0; ni < 4; ni++) {
            int col = colC + wc * 32 + ni * 8 + tig * 2;
            float bx = __ldg(&bias[col]), by = __ldg(&bias[col + 1]);
            float2 o0 = make_float2(acc[mi][ni][0] + bx, acc[mi][ni][1] + by);
            float2 o1 = make_float2(acc[mi][ni][2] + bx, acc[mi][ni][3] + by);
            if (RELU) {
                o0.x = fmaxf(o0.x, 0.f); o0.y = fmaxf(o0.y, 0.f);
                o1.x = fmaxf(o1.x, 0.f); o1.y = fmaxf(o1.y, 0.f);
            }
            *(float2*)(C + (size_t)row0 * N + col) = o0;
            *(float2*)(C + (size_t)(row0 + 8) * N + col) = o1;
        }
    }
}

// ---------------- per-batch attention (float4-vectorized) ----------------
__global__ __launch_bounds__(256)
void attn_kernel(const float* __restrict__ kvq, const float* __restrict__ Wattn,
                 const float* __restrict__ battn, float* __restrict__ attn_out) {
    int b = blockIdx.x;
    int tid = threadIdx.x;
    __shared__ float sk[AA * NKv];
    __shared__ float sq[AA * NQv];
    __shared__ float sv[AA * NVv];
    __shared__ float slog[AA][AA];
    __shared__ float swt[AA][AA + 1];
    __shared__ float skp[AA];
    const float* base = kvq + (size_t)b * AA * HH;
    {
        int a = tid >> 5, c = (tid & 31) * 4;
        *(float4*)&sk[a * NKv + c] = *(const float4*)&base[a * HH + c];
        *(float4*)&sq[a * NQv + c] = *(const float4*)&base[a * HH + 384 + c];
    }
    for (int i = tid; i < AA * NVv / 4; i += 256) {
        int a = i >> 6, c = (i & 63) * 4;
        *(float4*)&sv[a * NVv + c] = *(const float4*)&base[a * HH + 128 + c];
    }
    __syncthreads();
    int w = tid >> 5, lane = tid & 31;
    float kp = 0.f;
    for (int i = lane; i < AA * NKv; i += 32)
        kp += sk[i] * __ldg(&Wattn[(NQv + i) * AA + w]);
    #pragma unroll
    for (int o = 16; o; o >>= 1) kp += __shfl_xor_sync(0xFFFFFFFFu, kp, o);
    if (lane == 0) skp[w] = kp;
    __syncthreads();
    float accj[AA] = {0,0,0,0,0,0,0,0};
    for (int q = lane; q < NQv; q += 32) {
        float qv = sq[w * NQv + q];
        #pragma unroll
        for (int j = 0; j < AA; j++) accj[j] += qv * __ldg(&Wattn[q * AA + j]);
    }
    #pragma unroll
    for (int j = 0; j < AA; j++) {
        float v = accj[j];
        #pragma unroll
        for (int o = 16; o; o >>= 1) v += __shfl_xor_sync(0xFFFFFFFFu, v, o);
        if (lane == 0) slog[w][j] = v + skp[j] + __ldg(&battn[j]);
    }
    __syncthreads();
    if (tid < AA) {
        float m = -1e30f;
        #pragma unroll
        for (int j = 0; j < AA; j++) m = fmaxf(m, slog[tid][j]);
        float e[AA], s = 0.f;
        #pragma unroll
        for (int j = 0; j < AA; j++) { e[j] = expf(slog[tid][j] - m); s += e[j]; }
        #pragma unroll
        for (int j = 0; j < AA; j++) swt[tid][j] = e[j] / s;
    }
    __syncthreads();
    for (int idx = tid; idx < AA * NVv / 4; idx += 256) {
        int a = idx >> 6, v = (idx & 63) * 4;
        float4 acc = make_float4(0.f, 0.f, 0.f, 0.f);
        #pragma unroll
        for (int j = 0; j < AA; j++) {
            float wt = swt[a][j];
            float4 s4 = *(const float4*)&sv[j * NVv + v];
            acc.x += wt * s4.x; acc.y += wt * s4.y;
            acc.z += wt * s4.z; acc.w += wt * s4.w;
        }
        *(float4*)&attn_out[(size_t)(b * AA + a) * NVv + v] = acc;
    }
}

// ---------------- W2 head ----------------
__global__ __launch_bounds__(256)
void head_kernel(const float* __restrict__ comb, const float* __restrict__ W2,
                 const float* __restrict__ b2, float* __restrict__ out) {
    __shared__ float srow[8][HH];
    __shared__ float smx[8], smn[8];
    int w = threadIdx.x >> 5, lane = threadIdx.x & 31;
    int row = blockIdx.x * 8 + w;
    const float* a = comb + (size_t)row * HH;
    for (int i = lane * 4; i < HH; i += 128) *(float4*)&srow[w][i] = *(const float4*)&a[i];
    __syncwarp();
    float acc = 0.f;
    if (lane < NACT) {
        #pragma unroll 8
        for (int k = 0; k < HH; k++) acc += srow[w][k] * __ldg(&W2[k * NACT + lane]);
        acc += __ldg(&b2[lane]);
    }
    float be = (lane < NACT) ? fmaxf(acc, 0.f) : 0.f;
    if (lane < NACT) out[(size_t)row * NACT + lane] = be;
    float s = be;
    #pragma unroll
    for (int o = 16; o; o >>= 1) s += __shfl_xor_sync(0xFFFFFFFFu, s, o);
    s += (float)NACT;
    if (lane == 0) {
        int bb = row >> 3, aa = row & 7;
        out[ORI_OFF + aa * BB + bb] = (float)NACT / s;
    }
    float mx = be;
    float mn = (lane < NACT) ? be : 1e30f;
    #pragma unroll
    for (int o = 16; o; o >>= 1) {
        mx = fmaxf(mx, __shfl_xor_sync(0xFFFFFFFFu, mx, o));
        mn = fminf(mn, __shfl_xor_sync(0xFFFFFFFFu, mn, o));
    }
    if (lane == 0) { smx[w] = mx; smn[w] = mn; }
    __syncthreads();
    if (threadIdx.x == 0) {
        float M = -1e30f, m = 1e30f;
        #pragma unroll
        for (int i = 0; i < 8; i++) { M = fmaxf(M, smx[i]); m = fminf(m, smn[i]); }
        atomicMax(&g_scal[0], fkey(M));
        atomicMin(&g_scal[1], fkey(m));
    }
}

// ---------------- Dempster-Shafer scan ----------------
__global__ __launch_bounds__(256)
void ds_kernel(const float* __restrict__ out, float* __restrict__ allev) {
    __shared__ float smx[8], smn[8];
    int w = threadIdx.x >> 5, lane = threadIdx.x & 31;
    int b = blockIdx.x * 8 + w;
    float b0 = 0.f, u0 = 1.f;
    for (int a = 0; a < AA; a++) {
        float e = (lane < NACT) ? out[(size_t)(b * AA + a) * NACT + lane] : 0.f;
        float s = e;
        #pragma unroll
        for (int o = 16; o; o >>= 1) s += __shfl_xor_sync(0xFFFFFFFFu, s, o);
        s += (float)NACT;
        float b1 = e / s;
        float u1 = (float)NACT / s;
        float sum0 = b0, sum1 = b1, dot = b0 * b1;
        #pragma unroll
        for (int o = 16; o; o >>= 1) {
            sum0 += __shfl_xor_sync(0xFFFFFFFFu, sum0, o);
            sum1 += __shfl_xor_sync(0xFFFFFFFFu, sum1, o);
            dot  += __shfl_xor_sync(0xFFFFFFFFu, dot,  o);
        }
        float Cc = sum0 * sum1 - dot;
        float denom = 1.f - Cc;
        float nb = (b0 * b1 + b0 * u1 + b1 * u0) / denom;
        u0 = (u0 * u1) / denom;
        b0 = nb;
    }
    float ev = b0 * ((float)NACT / u0);
    if (lane < NACT) allev[(size_t)b * NACT + lane] = ev;
    float mx = (lane < NACT) ? ev : -1e30f;
    float mn = (lane < NACT) ? ev : 1e30f;
    #pragma unroll
    for (int o = 16; o; o >>= 1) {
        mx = fmaxf(mx, __shfl_xor_sync(0xFFFFFFFFu, mx, o));
        mn = fminf(mn, __shfl_xor_sync(0xFFFFFFFFu, mn, o));
    }
    if (lane == 0) { smx[w] = mx; smn[w] = mn; }
    __syncthreads();
    if (threadIdx.x == 0) {
        float M = -1e30f, m = 1e30f;
        #pragma unroll
        for (int i = 0; i < 8; i++) { M = fmaxf(M, smx[i]); m = fminf(m, smn[i]); }
        atomicMax(&g_scal[2], fkey(M));
        atomicMin(&g_scal[3], fkey(m));
    }
}

// ---------------- finalize ----------------
__global__ __launch_bounds__(256)
void fin_kernel(float* __restrict__ out, const float* __restrict__ allev) {
    float maxbe = funkey(g_scal[0]);
    float minbe = funkey(g_scal[1]);
    float maxre = funkey(g_scal[2]);
    float minre = funkey(g_scal[3]);
    float scale = (maxbe - minbe) * 0.1f;
    float norm = scale / (maxre - minre + 0.01f);
    int w = threadIdx.x >> 5, lane = threadIdx.x & 31;
    int row = blockIdx.x * 8 + w;
    int b = row >> 3, a = row & 7;
    float be = (lane < NACT) ? out[(size_t)row * NACT + lane] : 0.f;
    float ev = (lane < NACT) ? allev[(size_t)b * NACT + lane] : 0.f;
    float re = (ev - minre) * norm;
    float combined = be + re;
    if (lane < NACT) out[(size_t)row * NACT + lane] = be + combined;
    float s = (lane < NACT) ? combined : 0.f;
    #pragma unroll
    for (int o = 16; o; o >>= 1) s += __shfl_xor_sync(0xFFFFFFFFu, s, o);
    s += (float)NACT;
    if (lane == 0) out[COM_OFF + a * BB + b] = (float)NACT / s;
}

// ---------------- launch ----------------
extern "C" void kernel_launch(void* const* d_in, const int* in_sizes, int n_in,
                              void* d_out, int out_size) {
    const float* hidden = (const float*)d_in[0];
    const float* Wk    = (const float*)d_in[2];
    const float* bk    = (const float*)d_in[3];
    const float* Wv    = (const float*)d_in[4];
    const float* bv    = (const float*)d_in[5];
    const float* Wq    = (const float*)d_in[6];
    const float* bq    = (const float*)d_in[7];
    const float* Wattn = (const float*)d_in[8];
    const float* battn = (const float*)d_in[9];
    const float* Wc    = (const float*)d_in[10];
    const float* bc    = (const float*)d_in[11];
    const float* W2    = (const float*)d_in[12];
    const float* b2    = (const float*)d_in[13];
    float* out = (float*)d_out;

    float *kvq, *attn, *comb, *allev, *b1;
    __nv_bfloat16 *wt1h, *wt1l, *wtch, *wtcl;
    cudaGetSymbolAddress((void**)&kvq,   g_kvq);
    cudaGetSymbolAddress((void**)&attn,  g_attn);
    cudaGetSymbolAddress((void**)&comb,  g_comb);
    cudaGetSymbolAddress((void**)&allev, g_allev);
    cudaGetSymbolAddress((void**)&b1,    g_b1);
    cudaGetSymbolAddress((void**)&wt1h,  g_WT1h);
    cudaGetSymbolAddress((void**)&wt1l,  g_WT1l);
    cudaGetSymbolAddress((void**)&wtch,  g_WTch);
    cudaGetSymbolAddress((void**)&wtcl,  g_WTcl);

    init_kernel<<<1, 32>>>();
    pack1_kernel<<<(HH * HH + 255) / 256, 256>>>(Wk, bk, Wv, bv, Wq, bq);
    packc_kernel<<<(HH * (NVv + HH) + 255) / 256, 256>>>(Wc);

    dim3 g1(HH / 128, ROWS / 128);   // (4, 256)
    gemm_mma<false><<<g1, 256>>>(hidden, HH, HH, hidden, HH,
                                 wt1h, wt1l, b1, kvq, HH, HH);

    attn_kernel<<<BB, 256>>>(kvq, Wattn, battn, attn);

    gemm_mma<true><<<g1, 256>>>(attn, NVv, NVv, hidden, HH,
                                wtch, wtcl, bc, comb, HH, NVv + HH);

    head_kernel<<<ROWS / 8, 256>>>(comb, W2, b2, out);
    ds_kernel<<<BB / 8, 256>>>(out, allev);
    fin_kernel<<<ROWS / 8, 256>>>(out, allev);
}

// round 12
// speedup vs baseline: 2.3825x; 1.2102x over previous
#include <cuda_runtime.h>
#include <cuda_bf16.h>
#include <cstdint>

// Problem constants
#define BB   4096
#define AA   8
#define HH   512
#define NQv  128
#define NKv  128
#define NVv  256
#define NACT 30
#define ROWS (BB*AA)              // 32768
#define ORI_OFF  (ROWS*NACT)
#define COM_OFF  (ORI_OFF + ROWS)

// ---------------- device scratch (static, allocation-free) ----------------
__device__ float    g_kvq[(size_t)ROWS * HH];
__device__ float    g_attn[(size_t)ROWS * NVv];
__device__ float    g_comb[(size_t)ROWS * HH];
__device__ float    g_allev[(size_t)BB * NACT];
__device__ unsigned g_scal[4];
__device__ float    g_b1[HH];
// transposed, hi/lo bf16 weights: WT[n][k]
__device__ __nv_bfloat16 g_WT1h[HH * HH];
__device__ __nv_bfloat16 g_WT1l[HH * HH];
__device__ __nv_bfloat16 g_WTch[HH * (NVv + HH)];
__device__ __nv_bfloat16 g_WTcl[HH * (NVv + HH)];

// order-preserving float<->uint mapping for atomic min/max
__device__ __forceinline__ unsigned fkey(float f) {
    unsigned u = __float_as_uint(f);
    return (u >> 31) ? ~u : (u | 0x80000000u);
}
__device__ __forceinline__ float funkey(unsigned k) {
    unsigned u = (k >> 31) ? (k ^ 0x80000000u) : ~k;
    return __uint_as_float(u);
}

// bf16 mma.sync (family-portable HMMA)
__device__ __forceinline__ void mma_bf16(float* d, const uint32_t* a, const uint32_t* b) {
    asm volatile(
        "mma.sync.aligned.m16n8k16.row.col.f32.bf16.bf16.f32 "
        "{%0,%1,%2,%3}, {%4,%5,%6,%7}, {%8,%9}, {%0,%1,%2,%3};"
        : "+f"(d[0]), "+f"(d[1]), "+f"(d[2]), "+f"(d[3])
        : "r"(a[0]), "r"(a[1]), "r"(a[2]), "r"(a[3]), "r"(b[0]), "r"(b[1]));
}

__device__ __forceinline__ void cvt_hilo(float x, float y, uint32_t& hi, uint32_t& lo) {
    __nv_bfloat162 h = __floats2bfloat162_rn(x, y);
    float hx = __bfloat162float(h.x), hy = __bfloat162float(h.y);
    __nv_bfloat162 l = __floats2bfloat162_rn(x - hx, y - hy);
    hi = *(uint32_t*)&h;
    lo = *(uint32_t*)&l;
}

// ---------------- init ----------------
__global__ void init_kernel() {
    if (threadIdx.x == 0) {
        g_scal[0] = 0u; g_scal[1] = 0xFFFFFFFFu;
        g_scal[2] = 0u; g_scal[3] = 0xFFFFFFFFu;
    }
}

// ---------------- pack W1 (Wk|Wv|Wq) -> transposed hi/lo bf16, b1 ----------------
__global__ void pack1_kernel(const float* __restrict__ Wk, const float* __restrict__ bk,
                             const float* __restrict__ Wv, const float* __restrict__ bv,
                             const float* __restrict__ Wq, const float* __restrict__ bq) {
    int i = blockIdx.x * blockDim.x + threadIdx.x;
    if (i < HH * HH) {
        int n = i >> 9, k = i & 511;
        float w;
        if (n < NKv)            w = Wk[k * NKv + n];
        else if (n < NKv + NVv) w = Wv[k * NVv + (n - NKv)];
        else                    w = Wq[k * NQv + (n - NKv - NVv)];
        __nv_bfloat16 h = __float2bfloat16(w);
        g_WT1h[i] = h;
        g_WT1l[i] = __float2bfloat16(w - __bfloat162float(h));
    }
    if (i < HH) {
        float v;
        if (i < NKv)            v = bk[i];
        else if (i < NKv + NVv) v = bv[i - NKv];
        else                    v = bq[i - NKv - NVv];
        g_b1[i] = v;
    }
}

// ---------------- pack Wc -> transposed hi/lo bf16 ----------------
__global__ void packc_kernel(const float* __restrict__ Wc) {
    int i = blockIdx.x * blockDim.x + threadIdx.x;
    if (i < HH * (NVv + HH)) {
        int n = i / (NVv + HH), k = i % (NVv + HH);
        float w = Wc[k * HH + n];
        __nv_bfloat16 h = __float2bfloat16(w);
        g_WTch[i] = h;
        g_WTcl[i] = __float2bfloat16(w - __bfloat162float(h));
    }
}

// ---------------- HMMA GEMM: C[M,N] = act(A @ WT^T + bias) ----------------
// Block tile 128x128x32, 8 warps (2x4), warp tile 64x32.
// Double-buffered smem (2 x 40KB dynamic). B hi/lo via cp.async; A converted
// fp32->hi/lo bf16 through registers; one __syncthreads per chunk.
// hi/lo compensation: D += Ah*Bh + Ah*Bl + Al*Bh.
#define GSTR 40                      // padded k-stride in bf16 elems (80B, conflict-free)
#define TILE_B (128 * GSTR * 2)      // 10240 bytes per sub-tile
#define BUF_B  (4 * TILE_B)          // Ah|Al|Bh|Bl = 40960 bytes
#define GEMM_SMEM (2 * BUF_B)        // 81920

template<bool RELU>
__global__ __launch_bounds__(256, 2)
void gemm_mma(const float* __restrict__ A0, int lda0, int K0,
              const float* __restrict__ A1, int lda1,
              const __nv_bfloat16* __restrict__ WTh, const __nv_bfloat16* __restrict__ WTl,
              const float* __restrict__ bias, float* __restrict__ C, int N, int K) {
    extern __shared__ char sm[];
    uint32_t sbase = (uint32_t)__cvta_generic_to_shared(sm);
    int tid = threadIdx.x;
    int wid = tid >> 5, lane = tid & 31;
    int gid = lane >> 2, tig = lane & 3;
    int wr = wid >> 2, wc = wid & 3;           // 2 x 4 warp grid
    int rowC = blockIdx.y * 128;
    int colC = blockIdx.x * 128;

    int r = tid >> 1, kbase = (tid & 1) * 16;  // row r, 16 k-elems per thread

    float acc[4][4][4];
    #pragma unroll
    for (int mi = 0; mi < 4; mi++)
        #pragma unroll
        for (int ni = 0; ni < 4; ni++)
            #pragma unroll
            for (int j = 0; j < 4; j++) acc[mi][ni][j] = 0.f;

    float4 av[4];

    auto cpB = [&](int kb, int b) {
        const __nv_bfloat16* srch = WTh + (size_t)(colC + r) * K + kb + kbase;
        const __nv_bfloat16* srcl = WTl + (size_t)(colC + r) * K + kb + kbase;
        uint32_t off = (uint32_t)b * BUF_B + (uint32_t)(r * GSTR + kbase) * 2;
        uint32_t dh = sbase + 2 * TILE_B + off;
        uint32_t dl = sbase + 3 * TILE_B + off;
        asm volatile("cp.async.cg.shared.global [%0], [%1], 16;" :: "r"(dh),      "l"(srch));
        asm volatile("cp.async.cg.shared.global [%0], [%1], 16;" :: "r"(dh + 16), "l"(srch + 8));
        asm volatile("cp.async.cg.shared.global [%0], [%1], 16;" :: "r"(dl),      "l"(srcl));
        asm volatile("cp.async.cg.shared.global [%0], [%1], 16;" :: "r"(dl + 16), "l"(srcl + 8));
        asm volatile("cp.async.commit_group;");
    };
    auto loadA = [&](int kb) {
        const float* src; int lda;
        if (kb < K0) { src = A0 + kb; lda = lda0; }
        else         { src = A1 + (kb - K0); lda = lda1; }
        const float4* p = (const float4*)(src + (size_t)(rowC + r) * lda + kbase);
        av[0] = p[0]; av[1] = p[1]; av[2] = p[2]; av[3] = p[3];
    };
    auto storeA = [&](int b) {
        char* base = sm + b * BUF_B;
        #pragma unroll
        for (int i = 0; i < 4; i++) {
            int k = kbase + i * 4;
            uint32_t h01, l01, h23, l23;
            cvt_hilo(av[i].x, av[i].y, h01, l01);
            cvt_hilo(av[i].z, av[i].w, h23, l23);
            uint32_t off = (uint32_t)(r * GSTR + k) * 2;
            *(uint2*)(base + off)          = make_uint2(h01, h23);
            *(uint2*)(base + TILE_B + off) = make_uint2(l01, l23);
        }
    };
    auto compute = [&](int b) {
        const char* base = sm + b * BUF_B;
        const char* pAH = base;
        const char* pAL = base + TILE_B;
        const char* pBH = base + 2 * TILE_B;
        const char* pBL = base + 3 * TILE_B;
        int arow = wr * 64 + gid;
        int brow = wc * 32 + gid;
        #pragma unroll
        for (int ks = 0; ks < 32; ks += 16) {
            int ak = ks + tig * 2;
            uint32_t bh[4][2], bl[4][2];
            #pragma unroll
            for (int ni = 0; ni < 4; ni++) {
                uint32_t nb = (uint32_t)((brow + ni * 8) * GSTR + ak) * 2;
                bh[ni][0] = *(const uint32_t*)(pBH + nb);
                bh[ni][1] = *(const uint32_t*)(pBH + nb + 16);
                bl[ni][0] = *(const uint32_t*)(pBL + nb);
                bl[ni][1] = *(const uint32_t*)(pBL + nb + 16);
            }
            #pragma unroll
            for (int mi = 0; mi < 4; mi++) {
                uint32_t m0 = (uint32_t)((arow + mi * 16) * GSTR + ak) * 2;
                uint32_t m1 = m0 + 8 * GSTR * 2;
                uint32_t a[4], al[4];
                a[0] = *(const uint32_t*)(pAH + m0);
                a[1] = *(const uint32_t*)(pAH + m1);
                a[2] = *(const uint32_t*)(pAH + m0 + 16);
                a[3] = *(const uint32_t*)(pAH + m1 + 16);
                al[0] = *(const uint32_t*)(pAL + m0);
                al[1] = *(const uint32_t*)(pAL + m1);
                al[2] = *(const uint32_t*)(pAL + m0 + 16);
                al[3] = *(const uint32_t*)(pAL + m1 + 16);
                #pragma unroll
                for (int ni = 0; ni < 4; ni++) mma_bf16(acc[mi][ni], a,  bh[ni]);
                #pragma unroll
                for (int ni = 0; ni < 4; ni++) mma_bf16(acc[mi][ni], a,  bl[ni]);
                #pragma unroll
                for (int ni = 0; ni < 4; ni++) mma_bf16(acc[mi][ni], al, bh[ni]);
            }
        }
    };

    int nch = K / 32;
    // prologue: fill buffer 0
    cpB(0, 0);
    loadA(0);
    storeA(0);
    asm volatile("cp.async.wait_group 0;");
    __syncthreads();
    for (int c = 0; c < nch; c++) {
        if (c + 1 < nch) {
            cpB((c + 1) * 32, (c + 1) & 1);   // async B into other buffer
            loadA((c + 1) * 32);              // issue A LDGs (complete during compute)
        }
        compute(c & 1);
        if (c + 1 < nch) storeA((c + 1) & 1); // convert+store A into other buffer
        asm volatile("cp.async.wait_group 0;");
        __syncthreads();
    }

    // epilogue
    #pragma unroll
    for (int mi = 0; mi < 4; mi++) {
        int row0 = rowC + wr * 64 + mi * 16 + gid;
        #pragma unroll
        for (int ni = 0; ni < 4; ni++) {
            int col = colC + wc * 32 + ni * 8 + tig * 2;
            float bx = __ldg(&bias[col]), by = __ldg(&bias[col + 1]);
            float2 o0 = make_float2(acc[mi][ni][0] + bx, acc[mi][ni][1] + by);
            float2 o1 = make_float2(acc[mi][ni][2] + bx, acc[mi][ni][3] + by);
            if (RELU) {
                o0.x = fmaxf(o0.x, 0.f); o0.y = fmaxf(o0.y, 0.f);
                o1.x = fmaxf(o1.x, 0.f); o1.y = fmaxf(o1.y, 0.f);
            }
            *(float2*)(C + (size_t)row0 * N + col) = o0;
            *(float2*)(C + (size_t)(row0 + 8) * N + col) = o1;
        }
    }
}

// ---------------- per-batch attention (float4-vectorized) ----------------
__global__ __launch_bounds__(256)
void attn_kernel(const float* __restrict__ kvq, const float* __restrict__ Wattn,
                 const float* __restrict__ battn, float* __restrict__ attn_out) {
    int b = blockIdx.x;
    int tid = threadIdx.x;
    __shared__ float sk[AA * NKv];
    __shared__ float sq[AA * NQv];
    __shared__ float sv[AA * NVv];
    __shared__ float slog[AA][AA];
    __shared__ float swt[AA][AA + 1];
    __shared__ float skp[AA];
    const float* base = kvq + (size_t)b * AA * HH;
    {
        int a = tid >> 5, c = (tid & 31) * 4;
        *(float4*)&sk[a * NKv + c] = *(const float4*)&base[a * HH + c];
        *(float4*)&sq[a * NQv + c] = *(const float4*)&base[a * HH + 384 + c];
    }
    for (int i = tid; i < AA * NVv / 4; i += 256) {
        int a = i >> 6, c = (i & 63) * 4;
        *(float4*)&sv[a * NVv + c] = *(const float4*)&base[a * HH + 128 + c];
    }
    __syncthreads();
    int w = tid >> 5, lane = tid & 31;
    float kp = 0.f;
    for (int i = lane; i < AA * NKv; i += 32)
        kp += sk[i] * __ldg(&Wattn[(NQv + i) * AA + w]);
    #pragma unroll
    for (int o = 16; o; o >>= 1) kp += __shfl_xor_sync(0xFFFFFFFFu, kp, o);
    if (lane == 0) skp[w] = kp;
    __syncthreads();
    float accj[AA] = {0,0,0,0,0,0,0,0};
    for (int q = lane; q < NQv; q += 32) {
        float qv = sq[w * NQv + q];
        #pragma unroll
        for (int j = 0; j < AA; j++) accj[j] += qv * __ldg(&Wattn[q * AA + j]);
    }
    #pragma unroll
    for (int j = 0; j < AA; j++) {
        float v = accj[j];
        #pragma unroll
        for (int o = 16; o; o >>= 1) v += __shfl_xor_sync(0xFFFFFFFFu, v, o);
        if (lane == 0) slog[w][j] = v + skp[j] + __ldg(&battn[j]);
    }
    __syncthreads();
    if (tid < AA) {
        float m = -1e30f;
        #pragma unroll
        for (int j = 0; j < AA; j++) m = fmaxf(m, slog[tid][j]);
        float e[AA], s = 0.f;
        #pragma unroll
        for (int j = 0; j < AA; j++) { e[j] = expf(slog[tid][j] - m); s += e[j]; }
        #pragma unroll
        for (int j = 0; j < AA; j++) swt[tid][j] = e[j] / s;
    }
    __syncthreads();
    for (int idx = tid; idx < AA * NVv / 4; idx += 256) {
        int a = idx >> 6, v = (idx & 63) * 4;
        float4 acc = make_float4(0.f, 0.f, 0.f, 0.f);
        #pragma unroll
        for (int j = 0; j < AA; j++) {
            float wt = swt[a][j];
            float4 s4 = *(const float4*)&sv[j * NVv + v];
            acc.x += wt * s4.x; acc.y += wt * s4.y;
            acc.z += wt * s4.z; acc.w += wt * s4.w;
        }
        *(float4*)&attn_out[(size_t)(b * AA + a) * NVv + v] = acc;
    }
}

// ---------------- W2 head ----------------
__global__ __launch_bounds__(256)
void head_kernel(const float* __restrict__ comb, const float* __restrict__ W2,
                 const float* __restrict__ b2, float* __restrict__ out) {
    __shared__ float srow[8][HH];
    __shared__ float smx[8], smn[8];
    int w = threadIdx.x >> 5, lane = threadIdx.x & 31;
    int row = blockIdx.x * 8 + w;
    const float* a = comb + (size_t)row * HH;
    for (int i = lane * 4; i < HH; i += 128) *(float4*)&srow[w][i] = *(const float4*)&a[i];
    __syncwarp();
    float acc = 0.f;
    if (lane < NACT) {
        #pragma unroll 8
        for (int k = 0; k < HH; k++) acc += srow[w][k] * __ldg(&W2[k * NACT + lane]);
        acc += __ldg(&b2[lane]);
    }
    float be = (lane < NACT) ? fmaxf(acc, 0.f) : 0.f;
    if (lane < NACT) out[(size_t)row * NACT + lane] = be;
    float s = be;
    #pragma unroll
    for (int o = 16; o; o >>= 1) s += __shfl_xor_sync(0xFFFFFFFFu, s, o);
    s += (float)NACT;
    if (lane == 0) {
        int bb = row >> 3, aa = row & 7;
        out[ORI_OFF + aa * BB + bb] = (float)NACT / s;
    }
    float mx = be;
    float mn = (lane < NACT) ? be : 1e30f;
    #pragma unroll
    for (int o = 16; o; o >>= 1) {
        mx = fmaxf(mx, __shfl_xor_sync(0xFFFFFFFFu, mx, o));
        mn = fminf(mn, __shfl_xor_sync(0xFFFFFFFFu, mn, o));
    }
    if (lane == 0) { smx[w] = mx; smn[w] = mn; }
    __syncthreads();
    if (threadIdx.x == 0) {
        float M = -1e30f, m = 1e30f;
        #pragma unroll
        for (int i = 0; i < 8; i++) { M = fmaxf(M, smx[i]); m = fminf(m, smn[i]); }
        atomicMax(&g_scal[0], fkey(M));
        atomicMin(&g_scal[1], fkey(m));
    }
}

// ---------------- Dempster-Shafer scan ----------------
__global__ __launch_bounds__(256)
void ds_kernel(const float* __restrict__ out, float* __restrict__ allev) {
    __shared__ float smx[8], smn[8];
    int w = threadIdx.x >> 5, lane = threadIdx.x & 31;
    int b = blockIdx.x * 8 + w;
    float b0 = 0.f, u0 = 1.f;
    for (int a = 0; a < AA; a++) {
        float e = (lane < NACT) ? out[(size_t)(b * AA + a) * NACT + lane] : 0.f;
        float s = e;
        #pragma unroll
        for (int o = 16; o; o >>= 1) s += __shfl_xor_sync(0xFFFFFFFFu, s, o);
        s += (float)NACT;
        float b1 = e / s;
        float u1 = (float)NACT / s;
        float sum0 = b0, sum1 = b1, dot = b0 * b1;
        #pragma unroll
        for (int o = 16; o; o >>= 1) {
            sum0 += __shfl_xor_sync(0xFFFFFFFFu, sum0, o);
            sum1 += __shfl_xor_sync(0xFFFFFFFFu, sum1, o);
            dot  += __shfl_xor_sync(0xFFFFFFFFu, dot,  o);
        }
        float Cc = sum0 * sum1 - dot;
        float denom = 1.f - Cc;
        float nb = (b0 * b1 + b0 * u1 + b1 * u0) / denom;
        u0 = (u0 * u1) / denom;
        b0 = nb;
    }
    float ev = b0 * ((float)NACT / u0);
    if (lane < NACT) allev[(size_t)b * NACT + lane] = ev;
    float mx = (lane < NACT) ? ev : -1e30f;
    float mn = (lane < NACT) ? ev : 1e30f;
    #pragma unroll
    for (int o = 16; o; o >>= 1) {
        mx = fmaxf(mx, __shfl_xor_sync(0xFFFFFFFFu, mx, o));
        mn = fminf(mn, __shfl_xor_sync(0xFFFFFFFFu, mn, o));
    }
    if (lane == 0) { smx[w] = mx; smn[w] = mn; }
    __syncthreads();
    if (threadIdx.x == 0) {
        float M = -1e30f, m = 1e30f;
        #pragma unroll
        for (int i = 0; i < 8; i++) { M = fmaxf(M, smx[i]); m = fminf(m, smn[i]); }
        atomicMax(&g_scal[2], fkey(M));
        atomicMin(&g_scal[3], fkey(m));
    }
}

// ---------------- finalize ----------------
__global__ __launch_bounds__(256)
void fin_kernel(float* __restrict__ out, const float* __restrict__ allev) {
    float maxbe = funkey(g_scal[0]);
    float minbe = funkey(g_scal[1]);
    float maxre = funkey(g_scal[2]);
    float minre = funkey(g_scal[3]);
    float scale = (maxbe - minbe) * 0.1f;
    float norm = scale / (maxre - minre + 0.01f);
    int w = threadIdx.x >> 5, lane = threadIdx.x & 31;
    int row = blockIdx.x * 8 + w;
    int b = row >> 3, a = row & 7;
    float be = (lane < NACT) ? out[(size_t)row * NACT + lane] : 0.f;
    float ev = (lane < NACT) ? allev[(size_t)b * NACT + lane] : 0.f;
    float re = (ev - minre) * norm;
    float combined = be + re;
    if (lane < NACT) out[(size_t)row * NACT + lane] = be + combined;
    float s = (lane < NACT) ? combined : 0.f;
    #pragma unroll
    for (int o = 16; o; o >>= 1) s += __shfl_xor_sync(0xFFFFFFFFu, s, o);
    s += (float)NACT;
    if (lane == 0) out[COM_OFF + a * BB + b] = (float)NACT / s;
}

// ---------------- launch ----------------
extern "C" void kernel_launch(void* const* d_in, const int* in_sizes, int n_in,
                              void* d_out, int out_size) {
    const float* hidden = (const float*)d_in[0];
    const float* Wk    = (const float*)d_in[2];
    const float* bk    = (const float*)d_in[3];
    const float* Wv    = (const float*)d_in[4];
    const float* bv    = (const float*)d_in[5];
    const float* Wq    = (const float*)d_in[6];
    const float* bq    = (const float*)d_in[7];
    const float* Wattn = (const float*)d_in[8];
    const float* battn = (const float*)d_in[9];
    const float* Wc    = (const float*)d_in[10];
    const float* bc    = (const float*)d_in[11];
    const float* W2    = (const float*)d_in[12];
    const float* b2    = (const float*)d_in[13];
    float* out = (float*)d_out;

    float *kvq, *attn, *comb, *allev, *b1;
    __nv_bfloat16 *wt1h, *wt1l, *wtch, *wtcl;
    cudaGetSymbolAddress((void**)&kvq,   g_kvq);
    cudaGetSymbolAddress((void**)&attn,  g_attn);
    cudaGetSymbolAddress((void**)&comb,  g_comb);
    cudaGetSymbolAddress((void**)&allev, g_allev);
    cudaGetSymbolAddress((void**)&b1,    g_b1);
    cudaGetSymbolAddress((void**)&wt1h,  g_WT1h);
    cudaGetSymbolAddress((void**)&wt1l,  g_WT1l);
    cudaGetSymbolAddress((void**)&wtch,  g_WTch);
    cudaGetSymbolAddress((void**)&wtcl,  g_WTcl);

    cudaFuncSetAttribute(gemm_mma<false>, cudaFuncAttributeMaxDynamicSharedMemorySize, GEMM_SMEM);
    cudaFuncSetAttribute(gemm_mma<true>,  cudaFuncAttributeMaxDynamicSharedMemorySize, GEMM_SMEM);

    init_kernel<<<1, 32>>>();
    pack1_kernel<<<(HH * HH + 255) / 256, 256>>>(Wk, bk, Wv, bv, Wq, bq);
    packc_kernel<<<(HH * (NVv + HH) + 255) / 256, 256>>>(Wc);

    dim3 g1(HH / 128, ROWS / 128);   // (4, 256)
    gemm_mma<false><<<g1, 256, GEMM_SMEM>>>(hidden, HH, HH, hidden, HH,
                                            wt1h, wt1l, b1, kvq, HH, HH);

    attn_kernel<<<BB, 256>>>(kvq, Wattn, battn, attn);

    gemm_mma<true><<<g1, 256, GEMM_SMEM>>>(attn, NVv, NVv, hidden, HH,
                                           wtch, wtcl, bc, comb, HH, NVv + HH);

    head_kernel<<<ROWS / 8, 256>>>(comb, W2, b2, out);
    ds_kernel<<<BB / 8, 256>>>(out, allev);
    fin_kernel<<<ROWS / 8, 256>>>(out, allev);
}